// round 7
// baseline (speedup 1.0000x reference)
#include <cuda_runtime.h>
#include <cuda_bf16.h>
#include <cstdint>
#include <cstddef>

// ---------------- problem dims ----------------
#define BB 256
#define LL 196
#define EE 2048
#define DDIM 1024
#define AA 512

static constexpr int ROWS    = BB * LL;        // 50176
static constexpr int TILE_M  = 64;
static constexpr int NTILES  = ROWS / TILE_M;  // 784
static constexpr int KC      = 32;             // K per chunk
static constexpr int NCHUNK  = EE / KC;        // 64

// smem layout for k3 (dynamic): 2 stages of (A 64x36 + B 512x36) fp32
static constexpr int ROWPITCH_F = 36;                       // floats (144 B, conflict-free)
static constexpr int A_FLOATS   = TILE_M * ROWPITCH_F;      // 2304
static constexpr int B_FLOATS   = AA * ROWPITCH_F;          // 18432
static constexpr int STAGE_F    = A_FLOATS + B_FLOATS;      // 20736 floats = 82944 B
static constexpr int STAGE_B    = STAGE_F * 4;
static constexpr int SMEM_DYN   = 2 * STAGE_B;              // 165888

// ---------------- device scratch ----------------
__device__ __align__(16) float g_WeT[AA * EE];   // [a][e], tf32-RN rounded
__device__ __align__(16) float g_att2[BB * AA];  // dec@Wd + bd + be
__device__ __align__(16) float g_scores[ROWS];

// ---------------- helpers ----------------
__device__ __forceinline__ uint32_t smem_u32(const void* p) {
    uint32_t a;
    asm("{ .reg .u64 t; cvta.to.shared.u64 t, %1; cvt.u32.u64 %0, t; }" : "=r"(a) : "l"(p));
    return a;
}
__device__ __forceinline__ float to_tf32(float x) {
    uint32_t u;
    asm("cvt.rna.tf32.f32 %0, %1;" : "=r"(u) : "f"(x));
    return __uint_as_float(u);
}

#define CP_ASYNC16(dst_smem, src_gmem) \
    asm volatile("cp.async.cg.shared.global [%0], [%1], 16;" \
                 :: "r"(dst_smem), "l"(src_gmem))
#define CP_COMMIT()  asm volatile("cp.async.commit_group;" ::: "memory")
#define CP_WAIT_1()  asm volatile("cp.async.wait_group 1;" ::: "memory")
#define CP_WAIT_0()  asm volatile("cp.async.wait_group 0;" ::: "memory")

// m16n8k8 tf32 MMA (fp32 accum), D += A*B
__device__ __forceinline__ void mma_tf32(float* d, const uint32_t* a, const uint32_t* b) {
    asm volatile(
        "mma.sync.aligned.m16n8k8.row.col.f32.tf32.tf32.f32 "
        "{%0,%1,%2,%3}, {%4,%5,%6,%7}, {%8,%9}, {%0,%1,%2,%3};"
        : "+f"(d[0]), "+f"(d[1]), "+f"(d[2]), "+f"(d[3])
        : "r"(a[0]), "r"(a[1]), "r"(a[2]), "r"(a[3]), "r"(b[0]), "r"(b[1]));
}

__device__ __forceinline__ float fast_tanh(float x) {
    float e = __expf(-2.0f * fabsf(x));
    float t = __fdividef(1.0f - e, 1.0f + e);
    return copysignf(t, x);
}

// ---------------- kernel 1: transpose + tf32-RN round of We ----------------
__global__ void k_transpose_we(const float* __restrict__ We) {
    __shared__ float t[32][33];
    int e0 = blockIdx.x * 32;
    int a0 = blockIdx.y * 32;
    int tx = threadIdx.x;   // 0..31
    int ty = threadIdx.y;   // 0..7
#pragma unroll
    for (int i = 0; i < 4; i++)
        t[ty + i * 8][tx] = We[(size_t)(e0 + ty + i * 8) * AA + (a0 + tx)];
    __syncthreads();
#pragma unroll
    for (int i = 0; i < 4; i++)
        g_WeT[(size_t)(a0 + ty + i * 8) * EE + (e0 + tx)] = to_tf32(t[tx][ty + i * 8]);
}

// ---------------- kernel 2: att2 = dec @ Wd + bd + be ----------------
__global__ void k_att2(const float* __restrict__ dec, const float* __restrict__ Wd,
                       const float* __restrict__ bd, const float* __restrict__ be) {
    __shared__ float dec_s[4][DDIM];
    int b0 = blockIdx.x * 4;
    int tid = threadIdx.x;  // 0..511
    for (int i = tid; i < 4 * DDIM; i += 512)
        dec_s[i / DDIM][i % DDIM] = dec[(size_t)(b0 + i / DDIM) * DDIM + (i % DDIM)];
    __syncthreads();
    int a = tid;
    float acc0 = 0.f, acc1 = 0.f, acc2 = 0.f, acc3 = 0.f;
#pragma unroll 4
    for (int d = 0; d < DDIM; d++) {
        float w = Wd[(size_t)d * AA + a];
        acc0 += dec_s[0][d] * w;
        acc1 += dec_s[1][d] * w;
        acc2 += dec_s[2][d] * w;
        acc3 += dec_s[3][d] * w;
    }
    float bias = bd[a] + be[a];
    g_att2[(size_t)(b0 + 0) * AA + a] = acc0 + bias;
    g_att2[(size_t)(b0 + 1) * AA + a] = acc1 + bias;
    g_att2[(size_t)(b0 + 2) * AA + a] = acc2 + bias;
    g_att2[(size_t)(b0 + 3) * AA + a] = acc3 + bias;
}

// ---------------- kernel 3: tf32 GEMM + tanh + dot(wf) ----------------
__device__ __forceinline__ void issue_chunk(uint32_t sbase, const float* __restrict__ enc,
                                            int tile, int c, int tid) {
    uint32_t stb = sbase + (uint32_t)(c & 1) * STAGE_B;
    // A: enc rows [tile*64, +64), cols [c*32, +32)  -> 512 float4
#pragma unroll
    for (int i = 0; i < 2; i++) {
        int g4 = tid + i * 256;
        int row = g4 >> 3, seg = g4 & 7;
        const float* src = enc + (size_t)(tile * TILE_M + row) * EE + c * KC + seg * 4;
        CP_ASYNC16(stb + row * 144 + seg * 16, src);
    }
    // B: WeT rows [0,512), cols [c*32, +32) -> 4096 float4
#pragma unroll
    for (int i = 0; i < 16; i++) {
        int g4 = tid + i * 256;
        int row = g4 >> 3, seg = g4 & 7;
        const float* src = g_WeT + (size_t)row * EE + c * KC + seg * 4;
        CP_ASYNC16(stb + A_FLOATS * 4 + row * 144 + seg * 16, src);
    }
    CP_COMMIT();
}

__global__ void __launch_bounds__(256, 1)
k_gemm_score(const float* __restrict__ enc, const float* __restrict__ wf,
             const float* __restrict__ bf) {
    extern __shared__ float smemf[];
    __shared__ float wf_s[AA];
    __shared__ float redbuf[8][TILE_M];

    uint32_t sbase = smem_u32(smemf);
    int tid  = threadIdx.x;
    int w    = tid >> 5;          // warp 0..7 -> N block [w*64, +64)
    int lane = tid & 31;
    int g    = lane >> 2;         // 0..7
    int tq   = lane & 3;          // 0..3
    int tile = blockIdx.x;

    wf_s[tid]       = wf[tid];
    wf_s[tid + 256] = wf[tid + 256];

    float C[4][8][4];
#pragma unroll
    for (int mi = 0; mi < 4; mi++)
#pragma unroll
        for (int nj = 0; nj < 8; nj++)
#pragma unroll
            for (int k = 0; k < 4; k++) C[mi][nj][k] = 0.f;

    issue_chunk(sbase, enc, tile, 0, tid);
    issue_chunk(sbase, enc, tile, 1, tid);

    for (int c = 0; c < NCHUNK; c++) {
        if (c < NCHUNK - 1) { CP_WAIT_1(); } else { CP_WAIT_0(); }
        __syncthreads();

        const uint32_t* sA = reinterpret_cast<const uint32_t*>(smemf + (c & 1) * STAGE_F);
        const uint32_t* sB = sA + A_FLOATS;

#pragma unroll
        for (int kb = 0; kb < KC; kb += 8) {
            uint32_t af[4][4], bfg[8][2];
#pragma unroll
            for (int mi = 0; mi < 4; mi++) {
                int m0 = mi * 16;
                af[mi][0] = sA[(m0 + g)     * ROWPITCH_F + kb + tq];
                af[mi][1] = sA[(m0 + g + 8) * ROWPITCH_F + kb + tq];
                af[mi][2] = sA[(m0 + g)     * ROWPITCH_F + kb + tq + 4];
                af[mi][3] = sA[(m0 + g + 8) * ROWPITCH_F + kb + tq + 4];
            }
#pragma unroll
            for (int nj = 0; nj < 8; nj++) {
                int n0 = w * 64 + nj * 8;
                bfg[nj][0] = sB[(n0 + g) * ROWPITCH_F + kb + tq];
                bfg[nj][1] = sB[(n0 + g) * ROWPITCH_F + kb + tq + 4];
            }
#pragma unroll
            for (int mi = 0; mi < 4; mi++)
#pragma unroll
                for (int nj = 0; nj < 8; nj++)
                    mma_tf32(C[mi][nj], af[mi], bfg[nj]);
        }

        __syncthreads();
        if (c + 2 < NCHUNK) issue_chunk(sbase, enc, tile, c + 2, tid);
    }

    // epilogue: score[row] = sum_a tanh(att1 + att2) * wf[a]
    float rpart[8];
#pragma unroll
    for (int i = 0; i < 8; i++) rpart[i] = 0.f;

#pragma unroll
    for (int mi = 0; mi < 4; mi++) {
        int r0 = tile * TILE_M + mi * 16 + g;       // rows of c0/c1
        int r1 = r0 + 8;                            // rows of c2/c3
        const float* a2_0 = g_att2 + (size_t)(r0 / LL) * AA;
        const float* a2_1 = g_att2 + (size_t)(r1 / LL) * AA;
#pragma unroll
        for (int nj = 0; nj < 8; nj++) {
            int col = w * 64 + nj * 8 + tq * 2;
            float w0 = wf_s[col], w1 = wf_s[col + 1];
            rpart[mi * 2]     += fast_tanh(C[mi][nj][0] + __ldg(a2_0 + col))     * w0
                               + fast_tanh(C[mi][nj][1] + __ldg(a2_0 + col + 1)) * w1;
            rpart[mi * 2 + 1] += fast_tanh(C[mi][nj][2] + __ldg(a2_1 + col))     * w0
                               + fast_tanh(C[mi][nj][3] + __ldg(a2_1 + col + 1)) * w1;
        }
    }
#pragma unroll
    for (int d = 1; d < 4; d <<= 1)
#pragma unroll
        for (int i = 0; i < 8; i++)
            rpart[i] += __shfl_xor_sync(0xffffffffu, rpart[i], d);

    if (tq == 0) {
#pragma unroll
        for (int mi = 0; mi < 4; mi++) {
            redbuf[w][mi * 16 + g]     = rpart[mi * 2];
            redbuf[w][mi * 16 + g + 8] = rpart[mi * 2 + 1];
        }
    }
    __syncthreads();
    if (tid < TILE_M) {
        float s = __ldg(bf);
#pragma unroll
        for (int w2 = 0; w2 < 8; w2++) s += redbuf[w2][tid];
        g_scores[(size_t)tile * TILE_M + tid] = s;
    }
}

// ---------------- kernel 4: softmax + awe ----------------
__global__ void k_softmax_awe(const float* __restrict__ enc, const int* __restrict__ mask,
                              float* __restrict__ out_awe, float* __restrict__ out_alpha) {
    __shared__ float sal[LL];
    __shared__ float red[256];
    int b = blockIdx.x;
    int tid = threadIdx.x;

    float s = -3.4e38f;
    if (tid < LL) {
        s = g_scores[(size_t)b * LL + tid];
        if (mask[(size_t)b * LL + tid] == 0) s = -1e9f;
    }
    red[tid] = s;
    __syncthreads();
    for (int off = 128; off > 0; off >>= 1) {
        if (tid < off) red[tid] = fmaxf(red[tid], red[tid + off]);
        __syncthreads();
    }
    float m = red[0];
    __syncthreads();
    float p = (tid < LL) ? expf(s - m) : 0.f;
    red[tid] = p;
    __syncthreads();
    for (int off = 128; off > 0; off >>= 1) {
        if (tid < off) red[tid] += red[tid + off];
        __syncthreads();
    }
    float Z = red[0];
    float alpha = p / Z;
    if (tid < LL) {
        sal[tid] = alpha;
        out_alpha[(size_t)b * LL + tid] = alpha;
    }
    __syncthreads();

    const float* encb = enc + (size_t)b * LL * EE;
    for (int e = tid; e < EE; e += 256) {
        float acc = 0.f;
#pragma unroll 4
        for (int l = 0; l < LL; l++)
            acc += encb[(size_t)l * EE + e] * sal[l];
        out_awe[(size_t)b * EE + e] = acc;
    }
}

// ---------------- launcher ----------------
extern "C" void kernel_launch(void* const* d_in, const int* in_sizes, int n_in,
                              void* d_out, int out_size) {
    const float* enc  = (const float*)d_in[0];   // [256,196,2048]
    const float* dec  = (const float*)d_in[1];   // [256,1024]
    const int*   mask = (const int*)  d_in[2];   // [256,196]
    const float* We   = (const float*)d_in[3];   // [2048,512]
    const float* be   = (const float*)d_in[4];   // [512]
    const float* Wd   = (const float*)d_in[5];   // [1024,512]
    const float* bd   = (const float*)d_in[6];   // [512]
    const float* wf   = (const float*)d_in[7];   // [512]
    const float* bf   = (const float*)d_in[8];   // scalar

    float* out_awe   = (float*)d_out;                    // [256,2048]
    float* out_alpha = (float*)d_out + (size_t)BB * EE;  // [256,196]

    cudaFuncSetAttribute(k_gemm_score,
                         cudaFuncAttributeMaxDynamicSharedMemorySize, SMEM_DYN);

    k_transpose_we<<<dim3(EE / 32, AA / 32), dim3(32, 8)>>>(We);
    k_att2<<<BB / 4, 512>>>(dec, Wd, bd, be);
    k_gemm_score<<<NTILES, 256, SMEM_DYN>>>(enc, wf, bf);
    k_softmax_awe<<<BB, 256>>>(enc, mask, out_awe, out_alpha);
}

// round 8
// speedup vs baseline: 1.3903x; 1.3903x over previous
#include <cuda_runtime.h>
#include <cuda_bf16.h>
#include <cstdint>
#include <cstddef>

// ---------------- problem dims ----------------
#define BB 256
#define LL 196
#define EE 2048
#define DDIM 1024
#define AA 512

static constexpr int ROWS    = BB * LL;        // 50176
static constexpr int TILE_M  = 128;
static constexpr int NT      = ROWS / TILE_M;  // 392 tiles; x2 N-halves = 784 CTAs
static constexpr int KC      = 32;             // K per chunk
static constexpr int NCHUNK  = EE / KC;        // 64

// k3 smem: 3 stages of (A 128x36f + B packed 8192f)
static constexpr int A_PITCH_F = 36;                    // 144 B rows, conflict-free
static constexpr int A_F       = TILE_M * A_PITCH_F;    // 4608 floats (18432 B)
static constexpr int B_F       = 4 * 2048;              // 8192 floats (32768 B)
static constexpr int STAGE_F   = A_F + B_F;             // 12800 floats
static constexpr int STAGE_B   = STAGE_F * 4;           // 51200 B
static constexpr int NSTAGE    = 3;
static constexpr int SMEM_DYN  = NSTAGE * STAGE_B;      // 153600 B

// ---------------- device scratch ----------------
// We packed in m16n8k8 B-fragment order, tf32-RN rounded:
// idx = ((c*4 + kb)*32 + grp)*128 + lane*4 + slot
//   c=e>>5, kb=(e>>3)&3, grp=a>>4, lane=(a&7)*4+(e&3), slot=((a>>3)&1)*2+((e>>2)&1)
__device__ __align__(16) float g_WeB[AA * EE];
__device__ __align__(16) float g_att2[BB * AA];     // dec@Wd + bd + be
__device__ __align__(16) float g_spart[2 * ROWS];   // per-N-half partial scores

// ---------------- helpers ----------------
__device__ __forceinline__ uint32_t smem_u32(const void* p) {
    uint32_t a;
    asm("{ .reg .u64 t; cvta.to.shared.u64 t, %1; cvt.u32.u64 %0, t; }" : "=r"(a) : "l"(p));
    return a;
}
__device__ __forceinline__ float to_tf32(float x) {
    uint32_t u;
    asm("cvt.rna.tf32.f32 %0, %1;" : "=r"(u) : "f"(x));
    return __uint_as_float(u);
}

#define CP_ASYNC16(dst_smem, src_gmem) \
    asm volatile("cp.async.cg.shared.global [%0], [%1], 16;" \
                 :: "r"(dst_smem), "l"(src_gmem))
#define CP_COMMIT()  asm volatile("cp.async.commit_group;" ::: "memory")
#define CP_WAIT_2()  asm volatile("cp.async.wait_group 2;" ::: "memory")
#define CP_WAIT_1()  asm volatile("cp.async.wait_group 1;" ::: "memory")
#define CP_WAIT_0()  asm volatile("cp.async.wait_group 0;" ::: "memory")

// m16n8k8 tf32 MMA (fp32 accum), D += A*B
__device__ __forceinline__ void mma_tf32(float* d, const uint32_t* a,
                                         uint32_t b0, uint32_t b1) {
    asm volatile(
        "mma.sync.aligned.m16n8k8.row.col.f32.tf32.tf32.f32 "
        "{%0,%1,%2,%3}, {%4,%5,%6,%7}, {%8,%9}, {%0,%1,%2,%3};"
        : "+f"(d[0]), "+f"(d[1]), "+f"(d[2]), "+f"(d[3])
        : "r"(a[0]), "r"(a[1]), "r"(a[2]), "r"(a[3]), "r"(b0), "r"(b1));
}

__device__ __forceinline__ float fast_tanh(float x) {
    float e = __expf(-2.0f * fabsf(x));
    float t = __fdividef(1.0f - e, 1.0f + e);
    return copysignf(t, x);
}

// ---------------- kernel 1: We -> fragment-packed tf32 g_WeB ----------------
__global__ void k_pack_we(const float* __restrict__ We) {
    __shared__ float t[32][33];
    int e0 = blockIdx.x * 32;
    int a0 = blockIdx.y * 32;
    int tx = threadIdx.x;   // 0..31
    int ty = threadIdx.y;   // 0..7
#pragma unroll
    for (int i = 0; i < 4; i++)
        t[ty + i * 8][tx] = We[(size_t)(e0 + ty + i * 8) * AA + (a0 + tx)];
    __syncthreads();
    int a = a0 + tx;
#pragma unroll
    for (int i = 0; i < 4; i++) {
        int e = e0 + ty + i * 8;
        int c = e >> 5, kb = (e >> 3) & 3, grp = a >> 4;
        int lane = (a & 7) * 4 + (e & 3);
        int slot = ((a >> 3) & 1) * 2 + ((e >> 2) & 1);
        size_t idx = (size_t)(((c * 4 + kb) * 32 + grp)) * 128 + lane * 4 + slot;
        g_WeB[idx] = to_tf32(t[ty + i * 8][tx]);
    }
}

// ---------------- kernel 2: att2 = dec @ Wd + bd + be ----------------
__global__ void k_att2(const float* __restrict__ dec, const float* __restrict__ Wd,
                       const float* __restrict__ bd, const float* __restrict__ be) {
    __shared__ float dec_s[4][DDIM];
    int b0 = blockIdx.x * 4;
    int tid = threadIdx.x;  // 0..511
    for (int i = tid; i < 4 * DDIM; i += 512)
        dec_s[i / DDIM][i % DDIM] = dec[(size_t)(b0 + i / DDIM) * DDIM + (i % DDIM)];
    __syncthreads();
    int a = tid;
    float acc0 = 0.f, acc1 = 0.f, acc2 = 0.f, acc3 = 0.f;
#pragma unroll 4
    for (int d = 0; d < DDIM; d++) {
        float w = Wd[(size_t)d * AA + a];
        acc0 += dec_s[0][d] * w;
        acc1 += dec_s[1][d] * w;
        acc2 += dec_s[2][d] * w;
        acc3 += dec_s[3][d] * w;
    }
    float bias = bd[a] + be[a];
    g_att2[(size_t)(b0 + 0) * AA + a] = acc0 + bias;
    g_att2[(size_t)(b0 + 1) * AA + a] = acc1 + bias;
    g_att2[(size_t)(b0 + 2) * AA + a] = acc2 + bias;
    g_att2[(size_t)(b0 + 3) * AA + a] = acc3 + bias;
}

// ---------------- kernel 3: tf32 GEMM (M128 x N256 per CTA) + tanh + dot ----
__device__ __forceinline__ void issue_chunk(uint32_t sbase, const float* __restrict__ enc,
                                            int tile, int half, int c, int tid) {
    uint32_t stb = sbase + (uint32_t)(c % NSTAGE) * STAGE_B;
    // A: 128 rows x 32 floats = 1024 granules of 16B
#pragma unroll
    for (int i = 0; i < 4; i++) {
        int g4 = tid + i * 256;
        int row = g4 >> 3, seg = g4 & 7;
        const float* src = enc + (size_t)(tile * TILE_M + row) * EE + c * KC + seg * 4;
        CP_ASYNC16(stb + row * 144 + seg * 16, src);
    }
    // B: packed, 4 kb x 512 granules (linear per kb)
    const float* bsrc = g_WeB + (size_t)c * 16384 + half * 2048;
#pragma unroll
    for (int i = 0; i < 8; i++) {
        int g4 = tid + i * 256;
        int kb = g4 >> 9, off = g4 & 511;
        CP_ASYNC16(stb + 18432 + kb * 8192 + off * 16, bsrc + (size_t)kb * 4096 + off * 4);
    }
    CP_COMMIT();
}

__global__ void __launch_bounds__(256, 1)
k_gemm_score(const float* __restrict__ enc, const float* __restrict__ wf,
             const float* __restrict__ bf) {
    extern __shared__ float smemf[];
    __shared__ float wf_s[AA];
    __shared__ float redbuf[4][TILE_M];

    uint32_t sbase = smem_u32(smemf);
    int tid  = threadIdx.x;
    int w    = tid >> 5;
    int lane = tid & 31;
    int g    = lane >> 2;     // 0..7
    int tq   = lane & 3;      // 0..3
    int wm   = w >> 2;        // 0..1 (M half of CTA tile)
    int wn   = w & 3;         // 0..3 (N sub-block, 64 cols each)
    int bx   = blockIdx.x;
    int tile = bx >> 1;
    int half = bx & 1;        // N half: cols [half*256, +256)

    wf_s[tid]       = wf[tid];
    wf_s[tid + 256] = wf[tid + 256];

    float C[4][8][4];
#pragma unroll
    for (int mi = 0; mi < 4; mi++)
#pragma unroll
        for (int nj = 0; nj < 8; nj++)
#pragma unroll
            for (int k = 0; k < 4; k++) C[mi][nj][k] = 0.f;

    issue_chunk(sbase, enc, tile, half, 0, tid);
    issue_chunk(sbase, enc, tile, half, 1, tid);
    issue_chunk(sbase, enc, tile, half, 2, tid);

    for (int c = 0; c < NCHUNK; c++) {
        if (c < NCHUNK - 2)      { CP_WAIT_2(); }
        else if (c == NCHUNK - 2){ CP_WAIT_1(); }
        else                     { CP_WAIT_0(); }
        __syncthreads();

        const float* st = smemf + (c % NSTAGE) * STAGE_F;
        const uint32_t* sA = reinterpret_cast<const uint32_t*>(st);
        const float* sB = st + A_F;

#pragma unroll
        for (int kb = 0; kb < 4; kb++) {
            uint32_t af[4][4];
#pragma unroll
            for (int mi = 0; mi < 4; mi++) {
                int base = (wm * 64 + mi * 16 + g) * A_PITCH_F + kb * 8 + tq;
                af[mi][0] = sA[base];
                af[mi][1] = sA[base + 8 * A_PITCH_F];
                af[mi][2] = sA[base + 4];
                af[mi][3] = sA[base + 8 * A_PITCH_F + 4];
            }
            uint32_t bfg[8][2];
#pragma unroll
            for (int gi = 0; gi < 4; gi++) {
                float4 q = *reinterpret_cast<const float4*>(
                    sB + kb * 2048 + (wn * 4 + gi) * 128 + lane * 4);
                bfg[2 * gi][0]     = __float_as_uint(q.x);
                bfg[2 * gi][1]     = __float_as_uint(q.y);
                bfg[2 * gi + 1][0] = __float_as_uint(q.z);
                bfg[2 * gi + 1][1] = __float_as_uint(q.w);
            }
#pragma unroll
            for (int mi = 0; mi < 4; mi++)
#pragma unroll
                for (int nj = 0; nj < 8; nj++)
                    mma_tf32(C[mi][nj], af[mi], bfg[nj][0], bfg[nj][1]);
        }

        __syncthreads();
        if (c + NSTAGE < NCHUNK) issue_chunk(sbase, enc, tile, half, c + NSTAGE, tid);
    }

    // epilogue: partial score over this CTA's 256 columns
    float rpart[8];
#pragma unroll
    for (int i = 0; i < 8; i++) rpart[i] = 0.f;

#pragma unroll
    for (int mi = 0; mi < 4; mi++) {
        int r0 = tile * TILE_M + wm * 64 + mi * 16 + g;
        int r1 = r0 + 8;
        const float* a2_0 = g_att2 + (size_t)(r0 / LL) * AA;
        const float* a2_1 = g_att2 + (size_t)(r1 / LL) * AA;
#pragma unroll
        for (int nj = 0; nj < 8; nj++) {
            int col = half * 256 + wn * 64 + nj * 8 + tq * 2;
            float w0 = wf_s[col], w1 = wf_s[col + 1];
            rpart[mi * 2]     += fast_tanh(C[mi][nj][0] + __ldg(a2_0 + col))     * w0
                               + fast_tanh(C[mi][nj][1] + __ldg(a2_0 + col + 1)) * w1;
            rpart[mi * 2 + 1] += fast_tanh(C[mi][nj][2] + __ldg(a2_1 + col))     * w0
                               + fast_tanh(C[mi][nj][3] + __ldg(a2_1 + col + 1)) * w1;
        }
    }
#pragma unroll
    for (int d = 1; d < 4; d <<= 1)
#pragma unroll
        for (int i = 0; i < 8; i++)
            rpart[i] += __shfl_xor_sync(0xffffffffu, rpart[i], d);

    if (tq == 0) {
#pragma unroll
        for (int mi = 0; mi < 4; mi++) {
            redbuf[wn][wm * 64 + mi * 16 + g]     = rpart[mi * 2];
            redbuf[wn][wm * 64 + mi * 16 + g + 8] = rpart[mi * 2 + 1];
        }
    }
    __syncthreads();
    if (tid < TILE_M) {
        float s = redbuf[0][tid] + redbuf[1][tid] + redbuf[2][tid] + redbuf[3][tid];
        g_spart[(size_t)half * ROWS + tile * TILE_M + tid] = s;
    }
}

// ---------------- kernel 4a: softmax -> alpha ----------------
__global__ void k_softmax(const int* __restrict__ mask, const float* __restrict__ bf,
                          float* __restrict__ out_alpha) {
    __shared__ float red[256];
    int b = blockIdx.x;
    int tid = threadIdx.x;

    float s = -3.4e38f;
    if (tid < LL) {
        size_t r = (size_t)b * LL + tid;
        s = g_spart[r] + g_spart[ROWS + r] + __ldg(bf);
        if (mask[r] == 0) s = -1e9f;
    }
    red[tid] = s;
    __syncthreads();
    for (int off = 128; off > 0; off >>= 1) {
        if (tid < off) red[tid] = fmaxf(red[tid], red[tid + off]);
        __syncthreads();
    }
    float m = red[0];
    __syncthreads();
    float p = (tid < LL) ? expf(s - m) : 0.f;
    red[tid] = p;
    __syncthreads();
    for (int off = 128; off > 0; off >>= 1) {
        if (tid < off) red[tid] += red[tid + off];
        __syncthreads();
    }
    float Z = red[0];
    if (tid < LL) out_alpha[(size_t)b * LL + tid] = p / Z;
}

// ---------------- kernel 4b: awe = enc^T @ alpha ----------------
__global__ void __launch_bounds__(256)
k_awe(const float* __restrict__ enc, const float* __restrict__ alpha,
      float* __restrict__ out_awe) {
    __shared__ float sal[LL];
    int b  = blockIdx.y;
    int e0 = blockIdx.x * 1024 + threadIdx.x * 4;
    int tid = threadIdx.x;

    if (tid < LL) sal[tid] = alpha[(size_t)b * LL + tid];
    __syncthreads();

    const float* encb = enc + (size_t)b * LL * EE + e0;
    float a0 = 0.f, a1 = 0.f, a2 = 0.f, a3 = 0.f;
#pragma unroll 2
    for (int l = 0; l < LL; l++) {
        float4 v = *reinterpret_cast<const float4*>(encb + (size_t)l * EE);
        float al = sal[l];
        a0 += v.x * al; a1 += v.y * al; a2 += v.z * al; a3 += v.w * al;
    }
    float4 o; o.x = a0; o.y = a1; o.z = a2; o.w = a3;
    *reinterpret_cast<float4*>(out_awe + (size_t)b * EE + e0) = o;
}

// ---------------- launcher ----------------
extern "C" void kernel_launch(void* const* d_in, const int* in_sizes, int n_in,
                              void* d_out, int out_size) {
    const float* enc  = (const float*)d_in[0];   // [256,196,2048]
    const float* dec  = (const float*)d_in[1];   // [256,1024]
    const int*   mask = (const int*)  d_in[2];   // [256,196]
    const float* We   = (const float*)d_in[3];   // [2048,512]
    const float* be   = (const float*)d_in[4];   // [512]
    const float* Wd   = (const float*)d_in[5];   // [1024,512]
    const float* bd   = (const float*)d_in[6];   // [512]
    const float* wf   = (const float*)d_in[7];   // [512]
    const float* bf   = (const float*)d_in[8];   // scalar

    float* out_awe   = (float*)d_out;                    // [256,2048]
    float* out_alpha = (float*)d_out + (size_t)BB * EE;  // [256,196]

    cudaFuncSetAttribute(k_gemm_score,
                         cudaFuncAttributeMaxDynamicSharedMemorySize, SMEM_DYN);

    k_pack_we<<<dim3(EE / 32, AA / 32), dim3(32, 8)>>>(We);
    k_att2<<<BB / 4, 512>>>(dec, Wd, bd, be);
    k_gemm_score<<<NT * 2, 256, SMEM_DYN>>>(enc, wf, bf);
    k_softmax<<<BB, 256>>>(mask, bf, out_alpha);
    k_awe<<<dim3(2, BB), 256>>>(enc, out_alpha, out_awe);
}